// round 14
// baseline (speedup 1.0000x reference)
#include <cuda_runtime.h>

#define C_CLASS 32
#define S_SUP   16
#define D_DIM   1024
#define QB      16         // queries per CTA = warps per CTA
#define THREADS 512

// smem: scaled support tile [16][1024] + wsm2 (16 queries x 16 u64 weights)
#define SMEM_FLOATS (S_SUP*D_DIM + 2*QB*S_SUP + 16)
#define SMEM_BYTES  (SMEM_FLOATS * 4)

using u64 = unsigned long long;

__device__ __forceinline__ float fex2(float x){ float y; asm("ex2.approx.f32 %0,%1;" : "=f"(y) : "f"(x)); return y; }
__device__ __forceinline__ float frcp(float x){ float y; asm("rcp.approx.f32 %0,%1;" : "=f"(y) : "f"(x)); return y; }
__device__ __forceinline__ u64 mul2(u64 a, u64 b){ u64 r; asm("mul.rn.f32x2 %0,%1,%2;" : "=l"(r) : "l"(a), "l"(b)); return r; }
__device__ __forceinline__ u64 fma2(u64 a, u64 b, u64 c){ u64 r; asm("fma.rn.f32x2 %0,%1,%2,%3;" : "=l"(r) : "l"(a), "l"(b), "l"(c)); return r; }
__device__ __forceinline__ void unpack2(u64 p, float& lo, float& hi){ asm("mov.b64 {%0,%1},%2;" : "=f"(lo), "=f"(hi) : "l"(p)); }
__device__ __forceinline__ u64 pack2(float lo, float hi){ u64 p; asm("mov.b64 %0,{%1,%2};" : "=l"(p) : "f"(lo), "f"(hi)); return p; }

// a + b emitted as FFMA with IMMEDIATE multiplier 1.0 (a*1.0f + b).
// sm_103a FFMA-imm (src1-imm form 0x823) has rt_SMSP = 1 vs 2 for FADD:
// 2x fma-pipe throughput for the same result (exact: a*1.0 == a).
__device__ __forceinline__ float fadd_i(float a, float b){
    float d; asm("fma.rn.f32 %0,%1,0f3F800000,%2;" : "=f"(d) : "f"(a), "f"(b)); return d;
}

// Accumulate sum_{i<8} 1/(1 + 2^{z_i}) with ONE rcp.
// z packed via mul.rn.f32x2 (operands LDS.128-adjacent; unpack = aliasing).
// All scalar adds use FFMA-imm (rt 1). d = 1+t stays scalar per R12 lesson
// (packing MUFU outputs makes real MOVs). Support pre-scaled by -2*log2e so
// 2^z = e^{-2p}. No clamp: max |z| ~ 56 for N(0,1) -> P8 <= ~2^60 << 2^126.
__device__ __forceinline__ void acc8(float& acc, ulonglong2 sa, ulonglong2 sb,
                                     ulonglong2 qa, ulonglong2 qb) {
    u64 z01 = mul2(sa.x, qa.x);
    u64 z23 = mul2(sa.y, qa.y);
    u64 z45 = mul2(sb.x, qb.x);
    u64 z67 = mul2(sb.y, qb.y);
    float z0, z1, z2, z3, z4, z5, z6, z7;
    unpack2(z01, z0, z1);
    unpack2(z23, z2, z3);
    unpack2(z45, z4, z5);
    unpack2(z67, z6, z7);
    float d0 = fadd_i(fex2(z0), 1.0f);
    float d1 = fadd_i(fex2(z1), 1.0f);
    float d2 = fadd_i(fex2(z2), 1.0f);
    float d3 = fadd_i(fex2(z3), 1.0f);
    float d4 = fadd_i(fex2(z4), 1.0f);
    float d5 = fadd_i(fex2(z5), 1.0f);
    float d6 = fadd_i(fex2(z6), 1.0f);
    float d7 = fadd_i(fex2(z7), 1.0f);
    float p01 = d0 * d1, p23 = d2 * d3, p45 = d4 * d5, p67 = d6 * d7;
    float N4a = fmaf(p01, fadd_i(d2, d3), p23 * fadd_i(d0, d1));
    float N4b = fmaf(p45, fadd_i(d6, d7), p67 * fadd_i(d4, d5));
    float P4a = p01 * p23, P4b = p45 * p67;
    float rc  = frcp(P4a * P4b);
    float Num = fmaf(N4a, P4b, N4b * P4a);
    acc = fmaf(Num, rc, acc);
}

__global__ __launch_bounds__(THREADS, 2)
void instance_attention_kernel(const float* __restrict__ data,
                               float* __restrict__ out)
{
    extern __shared__ float sm[];
    float* cs   = sm;                       // support * (-2*log2e)  [16][1024]
    u64*   wsm2 = (u64*)(sm + S_SUP*D_DIM); // [16][16] duplicated weight pairs

    const int c    = blockIdx.y;
    const int qb   = blockIdx.x;
    const int tid  = threadIdx.x;
    const int w    = tid >> 5;
    const int lane = tid & 31;

    const float HSCALE   = -2.885390081777927f;   // -2*log2(e)
    const float TWOLOG2E =  2.885390081777927f;   // softmax fold (score = 2a + const)
    const float DESCALE  = -0.34657359027997264f; // 1/HSCALE: undo support pre-scale

    // ---- load scaled support tile ----
    const float4* supg = (const float4*)(data + (size_t)(c * S_SUP) * D_DIM);
    float4* cs4 = (float4*)cs;
    #pragma unroll
    for (int i = tid; i < S_SUP * D_DIM / 4; i += THREADS) {
        float4 v = supg[i];
        v.x *= HSCALE; v.y *= HSCALE; v.z *= HSCALE; v.w *= HSCALE;
        cs4[i] = v;
    }
    __syncthreads();

    // ---- this warp owns query qglob for the scoring phase ----
    const int qglob = qb * QB + w;
    const ulonglong2* qg2 = (const ulonglong2*)(data + (size_t)(C_CLASS * S_SUP + qglob) * D_DIM);
    const ulonglong2* cs_u2 = (const ulonglong2*)cs;

    // ---- 16 independent score accumulators (one per support row) ----
    float acc[16];
    #pragma unroll
    for (int r = 0; r < 16; ++r) acc[r] = 0.0f;

    // it-loop kept rolled: body = 16 acc8 (~18KB) fits L1.5 I$ (32KB);
    // query pair reloaded per iter (8 regs) — LDG L2-hit hidden by 16 chains.
    #pragma unroll 1
    for (int it = 0; it < 4; ++it) {
        const ulonglong2 qa  = qg2[(2 * it)     * 32 + lane];
        const ulonglong2 qbv = qg2[(2 * it + 1) * 32 + lane];
        const int i0 = it * 64 + lane;        // u2-granularity (16B) index
        const int i1 = i0 + 32;
        #pragma unroll
        for (int r = 0; r < 16; ++r) {
            const ulonglong2* row = cs_u2 + r * (D_DIM / 4);
            acc8(acc[r], row[i0], row[i1], qa, qbv);
        }
    }

    // ---- butterfly: every lane gets all 16 row sums ----
    #pragma unroll
    for (int off = 16; off; off >>= 1) {
        #pragma unroll
        for (int r = 0; r < 16; ++r)
            acc[r] += __shfl_xor_sync(0xffffffffu, acc[r], off);
    }

    // ---- in-register softmax (redundant per lane) ----
    // score = 2a - 1024 (affine): factor 2 folds into TWOLOG2E, const cancels.
    float m = acc[0];
    #pragma unroll
    for (int r = 1; r < 16; ++r) m = fmaxf(m, acc[r]);
    float ssum = 0.0f;
    #pragma unroll
    for (int r = 0; r < 16; ++r) {
        acc[r] = fex2((acc[r] - m) * TWOLOG2E);
        ssum += acc[r];
    }
    const float rs = frcp(ssum) * DESCALE;    // fold 1/sum + undo HSCALE

    // publish this query's 16 weights (duplicated pairs for f32x2)
    #pragma unroll
    for (int r = 0; r < 16; ++r) {
        if (lane == r) {
            float wv = acc[r] * rs;
            wsm2[w * 16 + r] = pack2(wv, wv);
        }
    }
    __syncthreads();

    // ---- epilogue: thread group grp (0/1) handles queries grp*8..grp*8+7
    //      over a 256-u2-column sweep (R11/R13-proven shape) ----
    const int grp   = tid >> 8;               // 0 or 1
    const int ci    = tid & 255;              // ulonglong2 column index
    const int qbase = grp * 8;

    u64 o0[8], o1[8];
    #pragma unroll
    for (int q = 0; q < 8; ++q) { o0[q] = 0ULL; o1[q] = 0ULL; }

    #pragma unroll
    for (int r2 = 0; r2 < 8; ++r2) {          // row pairs
        ulonglong2 va = cs_u2[(2 * r2)     * (D_DIM / 4) + ci];
        ulonglong2 vb = cs_u2[(2 * r2 + 1) * (D_DIM / 4) + ci];
        #pragma unroll
        for (int q = 0; q < 8; ++q) {
            ulonglong2 wpair = ((const ulonglong2*)(wsm2 + (qbase + q) * 16))[r2];
            o0[q] = fma2(wpair.x, va.x, o0[q]);
            o1[q] = fma2(wpair.x, va.y, o1[q]);
            o0[q] = fma2(wpair.y, vb.x, o0[q]);
            o1[q] = fma2(wpair.y, vb.y, o1[q]);
        }
    }

    #pragma unroll
    for (int q = 0; q < 8; ++q) {
        const int qg = qb * QB + qbase + q;
        ulonglong2* og = (ulonglong2*)(out + ((size_t)qg * C_CLASS + c) * D_DIM);
        og[ci] = make_ulonglong2(o0[q], o1[q]);
    }
}

extern "C" void kernel_launch(void* const* d_in, const int* in_sizes, int n_in,
                              void* d_out, int out_size)
{
    (void)in_sizes; (void)n_in; (void)out_size;
    const float* data = (const float*)d_in[0];
    float* out = (float*)d_out;

    cudaFuncSetAttribute(instance_attention_kernel,
                         cudaFuncAttributeMaxDynamicSharedMemorySize, SMEM_BYTES);

    dim3 grid(512 / QB, C_CLASS);   // (32 query-blocks, 32 classes)
    instance_attention_kernel<<<grid, THREADS, SMEM_BYTES>>>(data, out);
}

// round 15
// speedup vs baseline: 1.0459x; 1.0459x over previous
#include <cuda_runtime.h>

#define C_CLASS 32
#define S_SUP   16
#define D_DIM   1024
#define QB      16         // queries per CTA = warps per CTA
#define THREADS 512

// smem: scaled support tile [16][1024] + wsm2 (16 queries x 16 u64 weights)
#define SMEM_FLOATS (S_SUP*D_DIM + 2*QB*S_SUP + 16)
#define SMEM_BYTES  (SMEM_FLOATS * 4)

using u64 = unsigned long long;

__device__ __forceinline__ float fex2(float x){ float y; asm("ex2.approx.f32 %0,%1;" : "=f"(y) : "f"(x)); return y; }
__device__ __forceinline__ float frcp(float x){ float y; asm("rcp.approx.f32 %0,%1;" : "=f"(y) : "f"(x)); return y; }
__device__ __forceinline__ u64 mul2(u64 a, u64 b){ u64 r; asm("mul.rn.f32x2 %0,%1,%2;" : "=l"(r) : "l"(a), "l"(b)); return r; }
__device__ __forceinline__ u64 fma2(u64 a, u64 b, u64 c){ u64 r; asm("fma.rn.f32x2 %0,%1,%2,%3;" : "=l"(r) : "l"(a), "l"(b), "l"(c)); return r; }
__device__ __forceinline__ void unpack2(u64 p, float& lo, float& hi){ asm("mov.b64 {%0,%1},%2;" : "=f"(lo), "=f"(hi) : "l"(p)); }
__device__ __forceinline__ u64 pack2(float lo, float hi){ u64 p; asm("mov.b64 %0,{%1,%2};" : "=l"(p) : "f"(lo), "f"(hi)); return p; }

// Build N8, P8 for 8 elements of one support row such that
// sum_{i<8} 1/d_i = N8 / P8, d_i = 1 + 2^{z_i}, z_i = s_i*q_i (pre-scaled).
// z packed via mul.rn.f32x2 (operands LDS.128-adjacent; unpack = aliasing).
// No clamp: max |z| ~ 56 for N(0,1) data; d_i >= 1 so P never underflows.
__device__ __forceinline__ void np8(float& N8, float& P8,
                                    ulonglong2 sa, ulonglong2 sb,
                                    ulonglong2 qa, ulonglong2 qb) {
    u64 z01 = mul2(sa.x, qa.x);
    u64 z23 = mul2(sa.y, qa.y);
    u64 z45 = mul2(sb.x, qb.x);
    u64 z67 = mul2(sb.y, qb.y);
    float z0, z1, z2, z3, z4, z5, z6, z7;
    unpack2(z01, z0, z1);
    unpack2(z23, z2, z3);
    unpack2(z45, z4, z5);
    unpack2(z67, z6, z7);
    float d0 = 1.0f + fex2(z0);
    float d1 = 1.0f + fex2(z1);
    float d2 = 1.0f + fex2(z2);
    float d3 = 1.0f + fex2(z3);
    float d4 = 1.0f + fex2(z4);
    float d5 = 1.0f + fex2(z5);
    float d6 = 1.0f + fex2(z6);
    float d7 = 1.0f + fex2(z7);
    float p01 = d0 * d1, p23 = d2 * d3, p45 = d4 * d5, p67 = d6 * d7;
    float N4a = fmaf(p01, d2 + d3, p23 * (d0 + d1));
    float N4b = fmaf(p45, d6 + d7, p67 * (d4 + d5));
    float P4a = p01 * p23, P4b = p45 * p67;
    N8 = fmaf(N4a, P4b, N4b * P4a);
    P8 = P4a * P4b;
}

__global__ __launch_bounds__(THREADS, 2)
void instance_attention_kernel(const float* __restrict__ data,
                               float* __restrict__ out)
{
    extern __shared__ float sm[];
    float* cs   = sm;                       // support * (-2*log2e)  [16][1024]
    u64*   wsm2 = (u64*)(sm + S_SUP*D_DIM); // [16][16] duplicated weight pairs

    const int c    = blockIdx.y;
    const int qb   = blockIdx.x;
    const int tid  = threadIdx.x;
    const int w    = tid >> 5;
    const int lane = tid & 31;

    const float HSCALE   = -2.885390081777927f;   // -2*log2(e)
    const float TWOLOG2E =  2.885390081777927f;   // softmax fold (score = 2a + const)
    const float DESCALE  = -0.34657359027997264f; // 1/HSCALE: undo support pre-scale

    // ---- load scaled support tile ----
    const float4* supg = (const float4*)(data + (size_t)(c * S_SUP) * D_DIM);
    float4* cs4 = (float4*)cs;
    #pragma unroll
    for (int i = tid; i < S_SUP * D_DIM / 4; i += THREADS) {
        float4 v = supg[i];
        v.x *= HSCALE; v.y *= HSCALE; v.z *= HSCALE; v.w *= HSCALE;
        cs4[i] = v;
    }
    __syncthreads();

    // ---- this warp owns query qglob for the scoring phase ----
    const int qglob = qb * QB + w;
    const ulonglong2* qg2 = (const ulonglong2*)(data + (size_t)(C_CLASS * S_SUP + qglob) * D_DIM);
    const ulonglong2* cs_u2 = (const ulonglong2*)cs;

    // ---- 16 independent score accumulators (one per support row) ----
    float acc[16];
    #pragma unroll
    for (int r = 0; r < 16; ++r) acc[r] = 0.0f;

    // query slice loaded in two halves (16 regs instead of 32) to fit 64 regs
    // (R13-proven shape; R14's per-iter reload regressed)
    #pragma unroll 1
    for (int half = 0; half < 2; ++half) {
        ulonglong2 qv[4];
        #pragma unroll
        for (int it = 0; it < 4; ++it) qv[it] = qg2[(half * 4 + it) * 32 + lane];
        #pragma unroll
        for (int ot = 0; ot < 2; ++ot) {
            const int i0 = (half * 2 + ot) * 64 + lane;  // u2-granularity index
            const int i1 = i0 + 32;
            const ulonglong2 qa  = qv[2 * ot];
            const ulonglong2 qbv = qv[2 * ot + 1];
            // row PAIRS share one reciprocal: sumA = N8a/P8a, sumB = N8b/P8b,
            // rc = 1/(P8a*P8b) -> 1/P8a = P8b*rc, 1/P8b = P8a*rc.
            // Halves MUFU RCP count (9 -> 8.5 MUFU per 8 elems).
            #pragma unroll
            for (int rp = 0; rp < 8; ++rp) {
                const ulonglong2* rowA = cs_u2 + (2 * rp)     * (D_DIM / 4);
                const ulonglong2* rowB = cs_u2 + (2 * rp + 1) * (D_DIM / 4);
                float N8a, P8a, N8b, P8b;
                np8(N8a, P8a, rowA[i0], rowA[i1], qa, qbv);
                np8(N8b, P8b, rowB[i0], rowB[i1], qa, qbv);
                float rc   = frcp(P8a * P8b);
                float invA = P8b * rc;
                float invB = P8a * rc;
                acc[2 * rp]     = fmaf(N8a, invA, acc[2 * rp]);
                acc[2 * rp + 1] = fmaf(N8b, invB, acc[2 * rp + 1]);
            }
        }
    }

    // ---- butterfly: every lane gets all 16 row sums ----
    #pragma unroll
    for (int off = 16; off; off >>= 1) {
        #pragma unroll
        for (int r = 0; r < 16; ++r)
            acc[r] += __shfl_xor_sync(0xffffffffu, acc[r], off);
    }

    // ---- in-register softmax (redundant per lane) ----
    // score = 2a - 1024 (affine): factor 2 folds into TWOLOG2E, const cancels.
    float m = acc[0];
    #pragma unroll
    for (int r = 1; r < 16; ++r) m = fmaxf(m, acc[r]);
    float ssum = 0.0f;
    #pragma unroll
    for (int r = 0; r < 16; ++r) {
        acc[r] = fex2((acc[r] - m) * TWOLOG2E);
        ssum += acc[r];
    }
    const float rs = frcp(ssum) * DESCALE;    // fold 1/sum + undo HSCALE

    // publish this query's 16 weights (duplicated pairs for f32x2)
    #pragma unroll
    for (int r = 0; r < 16; ++r) {
        if (lane == r) {
            float wv = acc[r] * rs;
            wsm2[w * 16 + r] = pack2(wv, wv);
        }
    }
    __syncthreads();

    // ---- epilogue: thread group grp (0/1) handles queries grp*8..grp*8+7
    //      over a 256-u2-column sweep (R11/R13-proven shape) ----
    const int grp   = tid >> 8;               // 0 or 1
    const int ci    = tid & 255;              // ulonglong2 column index
    const int qbase = grp * 8;

    u64 o0[8], o1[8];
    #pragma unroll
    for (int q = 0; q < 8; ++q) { o0[q] = 0ULL; o1[q] = 0ULL; }

    #pragma unroll
    for (int r2 = 0; r2 < 8; ++r2) {          // row pairs
        ulonglong2 va = cs_u2[(2 * r2)     * (D_DIM / 4) + ci];
        ulonglong2 vb = cs_u2[(2 * r2 + 1) * (D_DIM / 4) + ci];
        #pragma unroll
        for (int q = 0; q < 8; ++q) {
            ulonglong2 wpair = ((const ulonglong2*)(wsm2 + (qbase + q) * 16))[r2];
            o0[q] = fma2(wpair.x, va.x, o0[q]);
            o1[q] = fma2(wpair.x, va.y, o1[q]);
            o0[q] = fma2(wpair.y, vb.x, o0[q]);
            o1[q] = fma2(wpair.y, vb.y, o1[q]);
        }
    }

    #pragma unroll
    for (int q = 0; q < 8; ++q) {
        const int qg = qb * QB + qbase + q;
        ulonglong2* og = (ulonglong2*)(out + ((size_t)qg * C_CLASS + c) * D_DIM);
        og[ci] = make_ulonglong2(o0[q], o1[q]);
    }
}

extern "C" void kernel_launch(void* const* d_in, const int* in_sizes, int n_in,
                              void* d_out, int out_size)
{
    (void)in_sizes; (void)n_in; (void)out_size;
    const float* data = (const float*)d_in[0];
    float* out = (float*)d_out;

    cudaFuncSetAttribute(instance_attention_kernel,
                         cudaFuncAttributeMaxDynamicSharedMemorySize, SMEM_BYTES);

    dim3 grid(512 / QB, C_CLASS);   // (32 query-blocks, 32 classes)
    instance_attention_kernel<<<grid, THREADS, SMEM_BYTES>>>(data, out);
}

// round 16
// speedup vs baseline: 1.1203x; 1.0712x over previous
#include <cuda_runtime.h>

#define C_CLASS 32
#define S_SUP   16
#define D_DIM   1024
#define QB      16         // queries per CTA = warps per CTA
#define THREADS 512

// smem: scaled support tile [16][1024] + wsm2 (16 queries x 16 u64 weights)
#define SMEM_FLOATS (S_SUP*D_DIM + 2*QB*S_SUP + 16)
#define SMEM_BYTES  (SMEM_FLOATS * 4)

using u64 = unsigned long long;

__device__ __forceinline__ float fex2(float x){ float y; asm("ex2.approx.f32 %0,%1;" : "=f"(y) : "f"(x)); return y; }
__device__ __forceinline__ float frcp(float x){ float y; asm("rcp.approx.f32 %0,%1;" : "=f"(y) : "f"(x)); return y; }
__device__ __forceinline__ u64 mul2(u64 a, u64 b){ u64 r; asm("mul.rn.f32x2 %0,%1,%2;" : "=l"(r) : "l"(a), "l"(b)); return r; }
__device__ __forceinline__ u64 fma2(u64 a, u64 b, u64 c){ u64 r; asm("fma.rn.f32x2 %0,%1,%2,%3;" : "=l"(r) : "l"(a), "l"(b), "l"(c)); return r; }
__device__ __forceinline__ void unpack2(u64 p, float& lo, float& hi){ asm("mov.b64 {%0,%1},%2;" : "=f"(lo), "=f"(hi) : "l"(p)); }
__device__ __forceinline__ u64 pack2(float lo, float hi){ u64 p; asm("mov.b64 %0,{%1,%2};" : "=l"(p) : "f"(lo), "f"(hi)); return p; }

// Build N8, P8 for 8 elements of one support row such that
// sum_{i<8} 1/d_i = N8 / P8, d_i = 1 + 2^{z_i}, z_i = s_i*q_i (pre-scaled).
// z packed via mul.rn.f32x2 (operands LDS.128-adjacent; unpack = aliasing).
// No clamp: max |z| ~ 56 for N(0,1) data; d_i >= 1 so P never underflows.
__device__ __forceinline__ void np8(float& N8, float& P8,
                                    ulonglong2 sa, ulonglong2 sb,
                                    ulonglong2 qa, ulonglong2 qb) {
    u64 z01 = mul2(sa.x, qa.x);
    u64 z23 = mul2(sa.y, qa.y);
    u64 z45 = mul2(sb.x, qb.x);
    u64 z67 = mul2(sb.y, qb.y);
    float z0, z1, z2, z3, z4, z5, z6, z7;
    unpack2(z01, z0, z1);
    unpack2(z23, z2, z3);
    unpack2(z45, z4, z5);
    unpack2(z67, z6, z7);
    float d0 = 1.0f + fex2(z0);
    float d1 = 1.0f + fex2(z1);
    float d2 = 1.0f + fex2(z2);
    float d3 = 1.0f + fex2(z3);
    float d4 = 1.0f + fex2(z4);
    float d5 = 1.0f + fex2(z5);
    float d6 = 1.0f + fex2(z6);
    float d7 = 1.0f + fex2(z7);
    float p01 = d0 * d1, p23 = d2 * d3, p45 = d4 * d5, p67 = d6 * d7;
    float N4a = fmaf(p01, d2 + d3, p23 * (d0 + d1));
    float N4b = fmaf(p45, d6 + d7, p67 * (d4 + d5));
    float P4a = p01 * p23, P4b = p45 * p67;
    N8 = fmaf(N4a, P4b, N4b * P4a);
    P8 = P4a * P4b;
}

__global__ __launch_bounds__(THREADS, 2)
void instance_attention_kernel(const float* __restrict__ data,
                               float* __restrict__ out)
{
    extern __shared__ float sm[];
    float* cs   = sm;                       // support * (-2*log2e)  [16][1024]
    u64*   wsm2 = (u64*)(sm + S_SUP*D_DIM); // [16][16] duplicated weight pairs

    const int c    = blockIdx.y;
    const int qb   = blockIdx.x;
    const int tid  = threadIdx.x;
    const int w    = tid >> 5;
    const int lane = tid & 31;

    const float HSCALE   = -2.885390081777927f;   // -2*log2(e)
    const float TWOLOG2E =  2.885390081777927f;   // softmax fold (score = 2a + const)
    const float DESCALE  = -0.34657359027997264f; // 1/HSCALE: undo support pre-scale

    // ---- load scaled support tile ----
    const float4* supg = (const float4*)(data + (size_t)(c * S_SUP) * D_DIM);
    float4* cs4 = (float4*)cs;
    #pragma unroll
    for (int i = tid; i < S_SUP * D_DIM / 4; i += THREADS) {
        float4 v = supg[i];
        v.x *= HSCALE; v.y *= HSCALE; v.z *= HSCALE; v.w *= HSCALE;
        cs4[i] = v;
    }
    __syncthreads();

    // ---- this warp owns query qglob for the scoring phase ----
    const int qglob = qb * QB + w;
    const ulonglong2* qg2 = (const ulonglong2*)(data + (size_t)(C_CLASS * S_SUP + qglob) * D_DIM);
    const ulonglong2* cs_u2 = (const ulonglong2*)cs;

    // ---- 16 independent score accumulators (one per support row) ----
    float acc[16];
    #pragma unroll
    for (int r = 0; r < 16; ++r) acc[r] = 0.0f;

    // query slice loaded in two halves (16 regs) — R13/R15-proven shape
    #pragma unroll 1
    for (int half = 0; half < 2; ++half) {
        ulonglong2 qv[4];
        #pragma unroll
        for (int it = 0; it < 4; ++it) qv[it] = qg2[(half * 4 + it) * 32 + lane];
        #pragma unroll
        for (int ot = 0; ot < 2; ++ot) {
            const int i0 = (half * 2 + ot) * 64 + lane;  // u2-granularity index
            const int i1 = i0 + 32;
            const ulonglong2 qa  = qv[2 * ot];
            const ulonglong2 qbv = qv[2 * ot + 1];
            // row PAIRS share one reciprocal (R15-proven)
            #pragma unroll
            for (int rp = 0; rp < 8; ++rp) {
                const ulonglong2* rowA = cs_u2 + (2 * rp)     * (D_DIM / 4);
                const ulonglong2* rowB = cs_u2 + (2 * rp + 1) * (D_DIM / 4);
                float N8a, P8a, N8b, P8b;
                np8(N8a, P8a, rowA[i0], rowA[i1], qa, qbv);
                np8(N8b, P8b, rowB[i0], rowB[i1], qa, qbv);
                float rc   = frcp(P8a * P8b);
                float invA = P8b * rc;
                float invB = P8a * rc;
                acc[2 * rp]     = fmaf(N8a, invA, acc[2 * rp]);
                acc[2 * rp + 1] = fmaf(N8b, invB, acc[2 * rp + 1]);
            }
        }
    }

    // ---- register-halving transpose-reduce: lane l ends with the FULL
    //      sum for row (l & 15), duplicated across 16-lane halves.
    //      Each step sums one lane-bit and halves the register count. ----
    float t8[8];
    {
        const bool hb = (lane & 1);
        #pragma unroll
        for (int k = 0; k < 8; ++k) {
            float send = hb ? acc[2*k]   : acc[2*k+1];
            float keep = hb ? acc[2*k+1] : acc[2*k];
            t8[k] = keep + __shfl_xor_sync(0xffffffffu, send, 1);
        }
    }
    float t4[4];
    {
        const bool hb = (lane & 2);
        #pragma unroll
        for (int k = 0; k < 4; ++k) {
            float send = hb ? t8[2*k]   : t8[2*k+1];
            float keep = hb ? t8[2*k+1] : t8[2*k];
            t4[k] = keep + __shfl_xor_sync(0xffffffffu, send, 2);
        }
    }
    float t2[2];
    {
        const bool hb = (lane & 4);
        #pragma unroll
        for (int k = 0; k < 2; ++k) {
            float send = hb ? t4[2*k]   : t4[2*k+1];
            float keep = hb ? t4[2*k+1] : t4[2*k];
            t2[k] = keep + __shfl_xor_sync(0xffffffffu, send, 4);
        }
    }
    float x;
    {
        const bool hb = (lane & 8);
        float send = hb ? t2[0] : t2[1];
        float keep = hb ? t2[1] : t2[0];
        x = keep + __shfl_xor_sync(0xffffffffu, send, 8);
    }
    x += __shfl_xor_sync(0xffffffffu, x, 16);   // row (lane&15) total, dup halves

    // ---- lane-parallel softmax over the 16 rows (offsets within halves) ----
    // score = 2a - 1024 (affine): factor 2 folds into TWOLOG2E, const cancels.
    float m = x;
    #pragma unroll
    for (int off = 8; off; off >>= 1)
        m = fmaxf(m, __shfl_xor_sync(0xffffffffu, m, off));
    float e = fex2((x - m) * TWOLOG2E);
    float ssum = e;
    #pragma unroll
    for (int off = 8; off; off >>= 1)
        ssum += __shfl_xor_sync(0xffffffffu, ssum, off);
    float wv = e * frcp(ssum) * DESCALE;        // fold 1/sum + undo HSCALE
    if (lane < 16) wsm2[w * 16 + lane] = pack2(wv, wv);
    __syncthreads();

    // ---- epilogue: thread handles 4 queries x 2 columns (LDS 80 -> 64) ----
    const int qset = tid >> 7;                  // 0..3 -> queries qset*4..+3
    const int c2   = tid & 127;                 // u2 column within half
    u64 oA0[4], oA1[4], oB0[4], oB1[4];         // [q] for col c2 / c2+128
    #pragma unroll
    for (int q = 0; q < 4; ++q) { oA0[q]=0ULL; oA1[q]=0ULL; oB0[q]=0ULL; oB1[q]=0ULL; }

    #pragma unroll
    for (int rp = 0; rp < 8; ++rp) {            // row pairs
        ulonglong2 wq[4];                       // weights hoisted per row-pair
        #pragma unroll
        for (int q = 0; q < 4; ++q)
            wq[q] = ((const ulonglong2*)(wsm2 + (qset * 4 + q) * 16))[rp];
        ulonglong2 vaA = cs_u2[(2 * rp)     * (D_DIM / 4) + c2];
        ulonglong2 vbA = cs_u2[(2 * rp + 1) * (D_DIM / 4) + c2];
        ulonglong2 vaB = cs_u2[(2 * rp)     * (D_DIM / 4) + 128 + c2];
        ulonglong2 vbB = cs_u2[(2 * rp + 1) * (D_DIM / 4) + 128 + c2];
        #pragma unroll
        for (int q = 0; q < 4; ++q) {
            oA0[q] = fma2(wq[q].x, vaA.x, oA0[q]);
            oA1[q] = fma2(wq[q].x, vaA.y, oA1[q]);
            oA0[q] = fma2(wq[q].y, vbA.x, oA0[q]);
            oA1[q] = fma2(wq[q].y, vbA.y, oA1[q]);
            oB0[q] = fma2(wq[q].x, vaB.x, oB0[q]);
            oB1[q] = fma2(wq[q].x, vaB.y, oB1[q]);
            oB0[q] = fma2(wq[q].y, vbB.x, oB0[q]);
            oB1[q] = fma2(wq[q].y, vbB.y, oB1[q]);
        }
    }

    #pragma unroll
    for (int q = 0; q < 4; ++q) {
        const int qg = qb * QB + qset * 4 + q;
        ulonglong2* og = (ulonglong2*)(out + ((size_t)qg * C_CLASS + c) * D_DIM);
        og[c2]       = make_ulonglong2(oA0[q], oA1[q]);
        og[128 + c2] = make_ulonglong2(oB0[q], oB1[q]);
    }
}

extern "C" void kernel_launch(void* const* d_in, const int* in_sizes, int n_in,
                              void* d_out, int out_size)
{
    (void)in_sizes; (void)n_in; (void)out_size;
    const float* data = (const float*)d_in[0];
    float* out = (float*)d_out;

    cudaFuncSetAttribute(instance_attention_kernel,
                         cudaFuncAttributeMaxDynamicSharedMemorySize, SMEM_BYTES);

    dim3 grid(512 / QB, C_CLASS);   // (32 query-blocks, 32 classes)
    instance_attention_kernel<<<grid, THREADS, SMEM_BYTES>>>(data, out);
}